// round 10
// baseline (speedup 1.0000x reference)
#include <cuda_runtime.h>
#include <cuda_bf16.h>
#include <cstdint>
#include <mma.h>

using namespace nvcuda;

// ---------------------------------------------------------------------------
// Problem constants
// ---------------------------------------------------------------------------
#define BATCH 16
#define LSEQ  1024
#define MROWS (BATCH*LSEQ)     // 16384
#define EDIM  192
#define DMODEL 196
#define DINNER 392
#define DSTATE 16
#define DTRANK 13
#define XZ_N   784             // 2*DINNER
#define XZ_LD  896             // 7 tiles of 128
#define DO_LD  256             // out-proj padded N (196 -> 2*128)
#define XD_LD  64              // x_dbl padded N (45 -> 64)
#define NCHUNK 16
#define CLEN   (LSEQ/NCHUNK)   // 64
#define SC_DL  16              // channels per fused-scan block

// ---------------------------------------------------------------------------
// Scratch (device globals: allocation-free per harness rules)
// ---------------------------------------------------------------------------
__device__ __align__(16) float g_tok[ (size_t)MROWS*EDIM ];        // patch-embed out
__device__ __align__(16) float g_h  [ (size_t)MROWS*DMODEL ];      // token stream (196)
__device__ __align__(16) float g_xz [2][ (size_t)MROWS*XZ_LD ];    // in-proj out (padded)
__device__ __align__(16) float g_xc [2][ (size_t)MROWS*DINNER ];   // conv+silu
__device__ __align__(16) float g_xd [2][ (size_t)MROWS*XD_LD ];    // x_dbl (padded)
__device__ __align__(16) float g_dl [2][ (size_t)MROWS*DINNER ];   // delta (softplus)
__device__ __align__(16) float g_BC [2][ (size_t)MROWS*32 ];       // [B(16) C(16)] aligned
__device__ __align__(16) float g_y  [2][ (size_t)MROWS*DINNER ];   // scan out (gated)
__device__ __align__(16) float g_do [2][ (size_t)MROWS*DO_LD ];    // out-proj (padded)
__device__ __align__(16) float g_stok[ MROWS ];                    // per-token cls partial

__device__ __forceinline__ float to_tf32(float x)
{
    float r;
    asm("cvt.rna.tf32.f32 %0, %1;" : "=f"(r) : "f"(x));
    return r;
}

// ---------------------------------------------------------------------------
// cp.async helpers
// ---------------------------------------------------------------------------
__device__ __forceinline__ void cp16(unsigned int dst, const void* src, int sz)
{
    asm volatile("cp.async.cg.shared.global [%0], [%1], 16, %2;\n"
                 :: "r"(dst), "l"(src), "r"(sz));
}
#define CP_COMMIT()  asm volatile("cp.async.commit_group;\n")
#define CP_WAIT0()   asm volatile("cp.async.wait_group 0;\n")
#define CP_WAIT1()   asm volatile("cp.async.wait_group 1;\n")

// ---------------------------------------------------------------------------
// tf32 WMMA GEMM, 128xBN tile, 8 warps (4x2), BK=32, cp.async double buffer,
// dynamic smem. For which==0 the A-loader gathers patches directly from the
// input image.  C[m,n] = sum_k A[m,k] * W[n,k]
// which: 0=patch (A=x gather, C=g_tok) 1=inproj (A=g_h,C=g_xz[z])
//        2=xdbl (A=g_xc[z],C=g_xd[z]) 3=outproj (A=g_y[z],C=g_do[z])
// flipmask bit z: read A rows with t -> 1023-t inside each 1024-row batch.
// ---------------------------------------------------------------------------
#define BK 32
#define SA_LD 36
#define GEMM_SMEM(BN) ((2*128*SA_LD + 2*(BN)*SA_LD)*4)

template<int BN>
__global__ void __launch_bounds__(256)
k_gemm(const float* __restrict__ W0, const float* __restrict__ W1,
       const float* __restrict__ xsrc,
       int which, int N, int K, int ldc, int flipmask)
{
    constexpr int NB = BN/32;                 // n-fragments per warp
    const int z = blockIdx.z;
    const float* __restrict__ W = z ? W1 : W0;
    const float* __restrict__ A;
    float* __restrict__ C;
    if      (which == 0) { A = xsrc;    C = g_tok;   }
    else if (which == 1) { A = g_h;     C = g_xz[z]; }
    else if (which == 2) { A = g_xc[z]; C = g_xd[z]; }
    else                 { A = g_y[z];  C = g_do[z]; }
    const bool flip = (flipmask >> z) & 1;

    extern __shared__ float dynsm[];
    float* sAb = dynsm;                       // [2][128][SA_LD]
    float* sBb = dynsm + 2*128*SA_LD;         // [2][BN][SA_LD]

    const int tid = threadIdx.x;              // 256 threads
    const int m0 = blockIdx.y * 128;
    const int n0 = blockIdx.x * BN;
    const int wid = tid >> 5;
    const int wm = wid >> 1, wn = wid & 1;    // 4x2 warp grid, 32 x BN/2 per warp

    wmma::fragment<wmma::accumulator,16,16,8,float> acc[2][NB];
    #pragma unroll
    for (int i=0;i<2;i++)
        #pragma unroll
        for (int j=0;j<NB;j++) wmma::fill_fragment(acc[i][j], 0.f);

    const int nc = (K + BK - 1) / BK;

    auto loadA = [&](int buf, int k0) {
        #pragma unroll
        for (int i=0;i<4;i++) {
            int f4 = tid + i*256;             // 0..1023
            int r = f4 >> 3, c4 = f4 & 7;
            int gm = m0 + r, gk = k0 + c4*4;
            unsigned int dst = (unsigned int)__cvta_generic_to_shared(
                &sAb[(buf*128 + r)*SA_LD + c4*4]);
            int sz = (gk < K) ? 16 : 0;
            const float* src;
            if (which == 0) {
                int b = gm >> 10, hw = gm & 1023;
                int hh = hw >> 5, ww = hw & 31;
                int cc = gk >> 6, rr = (gk >> 3) & 7, q = gk & 7;
                src = xsrc + (((size_t)(b*3 + cc)*256 + hh*8 + rr)*256 + ww*8 + q);
            } else {
                int row = flip ? ((gm & ~1023) | (1023 - (gm & 1023))) : gm;
                src = A + (size_t)row * K + gk;
            }
            if (!sz) src = A;
            cp16(dst, src, sz);
        }
    };
    auto loadB = [&](int buf, int k0) {
        #pragma unroll
        for (int i=0;i<BN/32;i++) {
            int f4 = tid + i*256;             // 0..BN*8-1
            int r = f4 >> 3, c4 = f4 & 7;
            int gn = n0 + r, gk = k0 + c4*4;
            const float* src = W + (size_t)gn * K + gk;
            int sz = (gn < N && gk < K) ? 16 : 0;
            if (!sz) src = W;
            cp16((unsigned int)__cvta_generic_to_shared(
                &sBb[(buf*BN + r)*SA_LD + c4*4]), src, sz);
        }
    };

    loadA(0, 0); loadB(0, 0); CP_COMMIT();

    for (int c = 0; c < nc; c++) {
        const int cur = c & 1;
        if (c + 1 < nc) {
            loadA(cur ^ 1, (c+1)*BK);
            loadB(cur ^ 1, (c+1)*BK);
            CP_COMMIT();
            CP_WAIT1();
        } else {
            CP_WAIT0();
        }
        __syncthreads();

        #pragma unroll
        for (int kk = 0; kk < BK; kk += 8) {
            wmma::fragment<wmma::matrix_a,16,16,8,wmma::precision::tf32,wmma::row_major> fa[2];
            wmma::fragment<wmma::matrix_b,16,16,8,wmma::precision::tf32,wmma::col_major> fb[NB];
            wmma::load_matrix_sync(fa[0], &sAb[(cur*128 + wm*32     )*SA_LD + kk], SA_LD);
            wmma::load_matrix_sync(fa[1], &sAb[(cur*128 + wm*32 + 16)*SA_LD + kk], SA_LD);
            #pragma unroll
            for (int j=0;j<NB;j++)
                wmma::load_matrix_sync(fb[j], &sBb[(cur*BN + wn*(BN/2) + j*16)*SA_LD + kk], SA_LD);
            #pragma unroll
            for (int i=0;i<2;i++)
                #pragma unroll
                for (int j=0;j<NB;j++)
                    wmma::mma_sync(acc[i][j], fa[i], fb[j], acc[i][j]);
        }
        __syncthreads();
    }

    #pragma unroll
    for (int i=0;i<2;i++)
        #pragma unroll
        for (int j=0;j<NB;j++)
            wmma::store_matrix_sync(&C[(size_t)(m0 + wm*32 + i*16) * ldc + (n0 + wn*(BN/2) + j*16)],
                                    acc[i][j], ldc, wmma::mem_row_major);
}

// ---------------------------------------------------------------------------
// LN + SiLU + positional encodings -> g_h. Warp-per-row (no block barriers).
// ---------------------------------------------------------------------------
__global__ void k_lnpe(const float* __restrict__ pb, const float* __restrict__ g,
                       const float* __restrict__ bb)
{
    const int m = blockIdx.x*8 + (threadIdx.x >> 5);
    const int lane = threadIdx.x & 31;
    float v[6];
    float s = 0.f, sq = 0.f;
    #pragma unroll
    for (int i=0;i<6;i++){
        int e = lane + 32*i;
        v[i] = g_tok[(size_t)m*EDIM + e] + pb[e];
        s += v[i]; sq += v[i]*v[i];
    }
    #pragma unroll
    for (int o=16;o;o>>=1){ s += __shfl_xor_sync(~0u, s, o); sq += __shfl_xor_sync(~0u, sq, o); }
    float mean = s * (1.f/EDIM);
    float var  = sq * (1.f/EDIM) - mean*mean;
    float rs = rsqrtf(var + 1e-5f);
    #pragma unroll
    for (int i=0;i<6;i++){
        int e = lane + 32*i;
        float u = (v[i]-mean)*rs*g[e] + bb[e];
        g_h[(size_t)m*DMODEL + e] = to_tf32(u / (1.f + __expf(-u)));
    }
    if (lane < 4) {
        int t = m & 1023;
        const float sc = 6.283185307179586f / 32.f;
        float val;
        if      (lane==0) val = sinf((float)t * sc);
        else if (lane==1) val = cosf((float)t * sc);
        else if (lane==2) val = sinf((float)(t>>5) * sc);
        else              val = cosf((float)(t>>5) * sc);
        g_h[(size_t)m*DMODEL + EDIM + lane] = to_tf32(val);
    }
}

// ---------------------------------------------------------------------------
// Causal depthwise conv (width 4) + bias + SiLU, t-blocked: each thread
// computes 8 consecutive timesteps of one channel (11 loads for 8 outputs).
// ---------------------------------------------------------------------------
__global__ void k_conv(const float* __restrict__ cw0, const float* __restrict__ cb0,
                       const float* __restrict__ cw1, const float* __restrict__ cb1)
{
    const int z = blockIdx.z;
    const int b = blockIdx.y;
    const int t0 = blockIdx.x * 8;
    const int d = threadIdx.x;            // 392 threads
    const float* __restrict__ cw = z ? cw1 : cw0;
    const float* __restrict__ cb = z ? cb1 : cb0;

    const float* base = g_xz[z] + ((size_t)(b*LSEQ + t0) * XZ_LD + d);
    float v[11];
    #pragma unroll
    for (int i=0;i<11;i++){
        int t = t0 + i - 3;
        v[i] = (t >= 0) ? base[(long)(i-3) * XZ_LD] : 0.f;
    }
    const float w0 = cw[d*4+0], w1 = cw[d*4+1], w2 = cw[d*4+2], w3 = cw[d*4+3];
    const float bias = cb[d];
    float* outp = g_xc[z] + ((size_t)(b*LSEQ + t0) * DINNER + d);
    #pragma unroll
    for (int j=0;j<8;j++){
        float acc = bias;
        acc = fmaf(w3, v[j+3], acc);
        acc = fmaf(w2, v[j+2], acc);
        acc = fmaf(w1, v[j+1], acc);
        acc = fmaf(w0, v[j  ], acc);
        outp[(size_t)j*DINNER] = to_tf32(acc / (1.f + __expf(-acc)));   // silu
    }
}

// ---------------------------------------------------------------------------
// delta = softplus(x_dbl[:,:13] @ dt_w.T + dt_b); also copy B,C into aligned g_BC
// ---------------------------------------------------------------------------
__global__ void k_deltabc(const float* __restrict__ dtw0, const float* __restrict__ dtb0,
                          const float* __restrict__ dtw1, const float* __restrict__ dtb1)
{
    const int z = blockIdx.z;
    const float* __restrict__ dtw = z ? dtw1 : dtw0;
    const float* __restrict__ dtb = z ? dtb1 : dtb0;
    long idx = (long)blockIdx.x*256 + threadIdx.x;
    if (idx >= (long)MROWS*DINNER) return;
    int m  = (int)(idx / DINNER);
    int dd = (int)(idx % DINNER);
    const float* xd = &g_xd[z][(size_t)m*XD_LD];
    float a = dtb[dd];
    #pragma unroll
    for (int r=0;r<DTRANK;r++) a = fmaf(xd[r], dtw[dd*DTRANK + r], a);
    float sp = fmaxf(a, 0.f) + log1pf(__expf(-fabsf(a)));
    g_dl[z][(size_t)m*DINNER + dd] = sp;
    if (dd < 32) g_BC[z][(size_t)m*32 + dd] = xd[DTRANK + dd];   // 13..44 = B(16),C(16)
}

// ---------------------------------------------------------------------------
// dA helper: structured A (A[n] = -(n+1)) uses one exp; generic uses 16.
// ---------------------------------------------------------------------------
template<bool STRUCT>
__device__ __forceinline__ void compute_dA(float dt, const float* __restrict__ A, float* dA)
{
    if (STRUCT) {
        const float r = __expf(-dt);
        const float r2 = r*r, r4 = r2*r2, r8 = r4*r4;
        dA[0]=r;       dA[1]=r2;      dA[2]=r2*r;      dA[3]=r4;
        dA[4]=r4*r;    dA[5]=r4*r2;   dA[6]=r4*dA[2];  dA[7]=r8;
        dA[8]=r8*r;    dA[9]=r8*r2;   dA[10]=r8*dA[2]; dA[11]=r8*r4;
        dA[12]=r8*dA[4]; dA[13]=r8*dA[5]; dA[14]=r8*dA[6]; dA[15]=r8*r8;
    } else {
        #pragma unroll
        for (int n=0;n<16;n++) dA[n] = __expf(dt * A[n]);
    }
}

__device__ __forceinline__ bool load_A(const float* __restrict__ al, int d, float* A)
{
    bool structured = true;
    #pragma unroll
    for (int n=0;n<16;n++){
        A[n] = -__expf(al[d*16+n]);
        structured = structured && (fabsf(A[n] + (float)(n+1)) < 1e-3f*(float)(n+1));
    }
    return structured;
}

// ---------------------------------------------------------------------------
// FUSED chunked scan: one block = (16 chunks) x (SC_DL channels) for one (z,b).
// Pass 1: per-chunk local scan from h=0 -> (h_loc, P) into smem.
// Carry:  half-warp (c==0) sequentially combines the 16 chunks in smem,
//         overwriting h_loc slots with the carry-in state per chunk.
// Pass 3: re-scan from carry-in, produce y = (C·h + D*xc)*silu(z_gate).
// Arithmetic order identical to the previous 3-kernel version.
// smem layout n-major: s[n][c][dl] -> conflict-free scalar access.
// ---------------------------------------------------------------------------
#define SIDX(n,c,dl) ((n)*(NCHUNK*SC_DL) + (c)*SC_DL + (dl))

template<bool STRUCT>
__device__ __forceinline__ void scan_fused_body(
    int z, int b, int c, int dl, int d, bool valid,
    const float* __restrict__ A, float Dd,
    float* __restrict__ s_h, float* __restrict__ s_P)
{
    const float* __restrict__ dP  = g_dl[z];
    const float* __restrict__ xcP = g_xc[z];
    const float* __restrict__ xzP = g_xz[z];
    const float4* __restrict__ bcP = (const float4*)g_BC[z];
    float* __restrict__ yP = g_y[z];

    const size_t rowbase = (size_t)b * LSEQ + (size_t)c * CLEN;

    // ---- pass 1: local scan ----
    {
        float h[16], P[16];
        #pragma unroll
        for (int n=0;n<16;n++){ h[n]=0.f; P[n]=1.f; }
        for (int t=0; t<CLEN; t++){
            const size_t row = rowbase + t;
            const float dt = dP [row*DINNER + d];
            const float xc = xcP[row*DINNER + d];
            const float4 B0 = bcP[row*8+0], B1 = bcP[row*8+1], B2 = bcP[row*8+2], B3 = bcP[row*8+3];
            const float du = dt * xc;
            float dA[16];
            compute_dA<STRUCT>(dt, A, dA);
            const float Bv[16] = {B0.x,B0.y,B0.z,B0.w, B1.x,B1.y,B1.z,B1.w,
                                  B2.x,B2.y,B2.z,B2.w, B3.x,B3.y,B3.z,B3.w};
            #pragma unroll
            for (int n=0;n<16;n++){
                h[n] = fmaf(dA[n], h[n], du * Bv[n]);
                P[n] *= dA[n];
            }
        }
        #pragma unroll
        for (int n=0;n<16;n++){
            s_h[SIDX(n,c,dl)] = h[n];
            s_P[SIDX(n,c,dl)] = P[n];
        }
    }
    __syncthreads();

    // ---- carry: sequential combine over chunks (threads with c==0) ----
    if (c == 0) {
        float hc[16];
        #pragma unroll
        for (int n=0;n<16;n++) hc[n] = 0.f;
        for (int cc=0; cc<NCHUNK; cc++){
            #pragma unroll
            for (int n=0;n<16;n++){
                const int idx = SIDX(n,cc,dl);
                float L  = s_h[idx];
                float Pv = s_P[idx];
                s_h[idx] = hc[n];                 // carry-in for chunk cc
                hc[n] = fmaf(Pv, hc[n], L);
            }
        }
    }
    __syncthreads();

    // ---- pass 3: re-scan from carry-in, emit y ----
    {
        float h[16];
        #pragma unroll
        for (int n=0;n<16;n++) h[n] = s_h[SIDX(n,c,dl)];

        for (int t=0; t<CLEN; t++){
            const size_t row = rowbase + t;
            const float dt = dP [row*DINNER + d];
            const float xc = xcP[row*DINNER + d];
            const float zv = xzP[row*XZ_LD + DINNER + d];
            const float4 B0 = bcP[row*8+0], B1 = bcP[row*8+1], B2 = bcP[row*8+2], B3 = bcP[row*8+3];
            const float4 C0 = bcP[row*8+4], C1 = bcP[row*8+5], C2 = bcP[row*8+6], C3 = bcP[row*8+7];
            const float du = dt * xc;
            float dA[16];
            compute_dA<STRUCT>(dt, A, dA);

            float a0=0.f, a1=0.f, a2=0.f, a3=0.f;
            #define STEP(n, Bc, Cc, ac) { \
                h[n] = fmaf(dA[n], h[n], du * (Bc)); \
                ac = fmaf(h[n], (Cc), ac); }
            STEP(0,  B0.x, C0.x, a0) STEP(1,  B0.y, C0.y, a1)
            STEP(2,  B0.z, C0.z, a2) STEP(3,  B0.w, C0.w, a3)
            STEP(4,  B1.x, C1.x, a0) STEP(5,  B1.y, C1.y, a1)
            STEP(6,  B1.z, C1.z, a2) STEP(7,  B1.w, C1.w, a3)
            STEP(8,  B2.x, C2.x, a0) STEP(9,  B2.y, C2.y, a1)
            STEP(10, B2.z, C2.z, a2) STEP(11, B2.w, C2.w, a3)
            STEP(12, B3.x, C3.x, a0) STEP(13, B3.y, C3.y, a1)
            STEP(14, B3.z, C3.z, a2) STEP(15, B3.w, C3.w, a3)
            #undef STEP
            float y = ((a0+a1)+(a2+a3)) + Dd*xc;
            float sg = 1.f / (1.f + __expf(-zv));
            if (valid) yP[row*DINNER + d] = to_tf32(y * (zv * sg));
        }
    }
}

__global__ void __launch_bounds__(NCHUNK*SC_DL)
k_scanall(const float* __restrict__ al0, const float* __restrict__ Dp0,
          const float* __restrict__ al1, const float* __restrict__ Dp1)
{
    __shared__ float s_h[16*NCHUNK*SC_DL];   // 16 states x 16 chunks x 16 ch
    __shared__ float s_P[16*NCHUNK*SC_DL];   // 16KB + 16KB

    const int z = blockIdx.z;
    const int b = blockIdx.y;
    const int dl = threadIdx.x & (SC_DL-1);
    const int c  = threadIdx.x / SC_DL;      // chunk 0..15
    int d = blockIdx.x*SC_DL + dl;
    const bool valid = (d < DINNER);
    if (!valid) d = DINNER-1;

    float A[16];
    const bool st = load_A(z ? al1 : al0, d, A);
    const float Dd = (z ? Dp1 : Dp0)[d];

    if (st) scan_fused_body<true >(z, b, c, dl, d, valid, A, Dd, s_h, s_P);
    else    scan_fused_body<false>(z, b, c, dl, d, valid, A, Dd, s_h, s_P);
}

// ---------------------------------------------------------------------------
// Combine directions + LN + SiLU + residual + cls dot. Warp-per-token.
// ---------------------------------------------------------------------------
__global__ void k_combine(const float* __restrict__ blg, const float* __restrict__ blb,
                          const float* __restrict__ cw)
{
    const int m = blockIdx.x*8 + (threadIdx.x >> 5);
    const int lane = threadIdx.x & 31;
    const int mf = (m & ~1023) | (1023 - (m & 1023));
    float u[7];
    float s = 0.f, sq = 0.f;
    #pragma unroll
    for (int i=0;i<7;i++){
        int e = lane + 32*i;
        float x = 0.f;
        if (e < DMODEL){
            float fo = g_do[0][(size_t)m *DO_LD + e];
            float bo = g_do[1][(size_t)mf*DO_LD + e];
            x = 0.5f*(fo + bo);
            s += x; sq += x*x;
        }
        u[i] = x;
    }
    #pragma unroll
    for (int o=16;o;o>>=1){ s += __shfl_xor_sync(~0u, s, o); sq += __shfl_xor_sync(~0u, sq, o); }
    float mean = s * (1.f/DMODEL);
    float var  = sq * (1.f/DMODEL) - mean*mean;
    float rs = rsqrtf(var + 1e-5f);
    float p = 0.f;
    #pragma unroll
    for (int i=0;i<7;i++){
        int e = lane + 32*i;
        if (e < DMODEL){
            float v = (u[i]-mean)*rs*blg[e] + blb[e];
            v = v / (1.f + __expf(-v));                  // silu
            v += g_h[(size_t)m*DMODEL + e];              // residual
            p = fmaf(v, cw[e], p);
        }
    }
    #pragma unroll
    for (int o=16;o;o>>=1) p += __shfl_xor_sync(~0u, p, o);
    if (lane == 0) g_stok[m] = p;
}

__global__ void k_final(const float* __restrict__ cb, float* __restrict__ out)
{
    const int b = blockIdx.x;
    const int tid = threadIdx.x;   // 256
    __shared__ float sm[8];
    float s = 0.f;
    for (int i = tid; i < LSEQ; i += 256) s += g_stok[b*LSEQ + i];
    #pragma unroll
    for (int o=16;o;o>>=1) s += __shfl_xor_sync(~0u, s, o);
    if ((tid&31)==0) sm[tid>>5] = s;
    __syncthreads();
    if (tid == 0){
        float t = 0.f;
        #pragma unroll
        for (int i=0;i<8;i++) t += sm[i];
        out[b] = cb[0] + t * (1.f/LSEQ);
    }
}

// ---------------------------------------------------------------------------
// Host launcher
// ---------------------------------------------------------------------------
extern "C" void kernel_launch(void* const* d_in, const int* in_sizes, int n_in,
                              void* d_out, int out_size)
{
    const float* p[27];
    for (int i=0;i<27 && i<n_in;i++) p[i] = (const float*)d_in[i];

    const float *x, *pw, *pb, *peg, *peb, *blg, *blb, *cw, *cb;
    const float *fw[9], *bw[9];
    // fw/bw order: in_w, conv_w, conv_b, xp_w, dt_w, dt_b, A_log, D, out_w
    if (in_sizes[5] == XZ_N*DMODEL) {
        x=p[0]; pw=p[1]; pb=p[2]; peg=p[3]; peb=p[4];
        for (int i=0;i<9;i++){ fw[i]=p[5+i]; bw[i]=p[14+i]; }
        blg=p[23]; blb=p[24]; cw=p[25]; cb=p[26];
    } else {
        x=p[0]; pw=p[1]; pb=p[2]; peg=p[3]; peb=p[4];
        blg=p[5]; blb=p[6]; cw=p[7]; cb=p[8];
        for (int i=0;i<9;i++){ fw[i]=p[9+i]; bw[i]=p[18+i]; }
    }
    float* out = (float*)d_out;

    static bool attr_set = false;
    if (!attr_set) {
        cudaFuncSetAttribute(k_gemm<64>,  cudaFuncAttributeMaxDynamicSharedMemorySize, GEMM_SMEM(64));
        cudaFuncSetAttribute(k_gemm<128>, cudaFuncAttributeMaxDynamicSharedMemorySize, GEMM_SMEM(128));
        attr_set = true;
    }

    // 1. patch embed GEMM (fused gather): M=16384, N=192, K=192
    k_gemm<64><<<dim3(3, MROWS/128, 1), 256, GEMM_SMEM(64)>>>(pw, pw, x, 0, EDIM, EDIM, EDIM, 0);
    // 2. LN + silu + positional enc (warp per row)
    k_lnpe<<<MROWS/8, 256>>>(pb, peg, peb);
    // 3. in-proj both dirs: N=784, K=196; backward (z=1) reads flipped rows
    k_gemm<128><<<dim3(7, MROWS/128, 2), 256, GEMM_SMEM(128)>>>(fw[0], bw[0], x, 1, XZ_N, DMODEL, XZ_LD, 2);
    // 4. depthwise conv + silu (t-blocked: 8 timesteps/thread)
    k_conv<<<dim3(LSEQ/8, BATCH, 2), DINNER>>>(fw[1], fw[2], bw[1], bw[2]);
    // 5. x_dbl GEMM: N=45, K=392
    k_gemm<64><<<dim3(1, MROWS/128, 2), 256, GEMM_SMEM(64)>>>(fw[3], bw[3], x, 2, DTRANK + 2*DSTATE, DINNER, XD_LD, 0);
    // 6. delta (softplus) + pack B,C
    {
        long n = (long)MROWS*DINNER;
        k_deltabc<<<dim3((unsigned)((n + 255)/256), 1, 2), 256>>>(fw[4], fw[5], bw[4], bw[5]);
    }
    // 7. fused chunked selective scan (both dirs): local + carry + final in one
    k_scanall<<<dim3((DINNER + SC_DL - 1)/SC_DL, BATCH, 2), NCHUNK*SC_DL>>>(fw[6], fw[7], bw[6], bw[7]);
    // 8. out-proj: N=196, K=392
    k_gemm<128><<<dim3(2, MROWS/128, 2), 256, GEMM_SMEM(128)>>>(fw[8], bw[8], x, 3, DMODEL, DINNER, DO_LD, 0);
    // 9. combine + LN + silu + residual + cls dot per token (warp per token)
    k_combine<<<MROWS/8, 256>>>(blg, blb, cw);
    // 10. final reduction over tokens
    k_final<<<BATCH, 256>>>(cb, out);
}

// round 11
// speedup vs baseline: 1.3930x; 1.3930x over previous
#include <cuda_runtime.h>
#include <cuda_bf16.h>
#include <cstdint>
#include <mma.h>

using namespace nvcuda;

// ---------------------------------------------------------------------------
// Problem constants
// ---------------------------------------------------------------------------
#define BATCH 16
#define LSEQ  1024
#define MROWS (BATCH*LSEQ)     // 16384
#define EDIM  192
#define DMODEL 196
#define DINNER 392
#define DSTATE 16
#define DTRANK 13
#define XZ_N   784             // 2*DINNER
#define XZ_LD  896             // 7 tiles of 128
#define DO_LD  256             // out-proj padded N (196 -> 2*128)
#define XD_LD  64              // x_dbl padded N (45 -> 64)
#define NCHUNK 16
#define CLEN   (LSEQ/NCHUNK)   // 64

// ---------------------------------------------------------------------------
// Scratch (device globals: allocation-free per harness rules)
// ---------------------------------------------------------------------------
__device__ __align__(16) float g_tok[ (size_t)MROWS*EDIM ];        // patch-embed out
__device__ __align__(16) float g_h  [ (size_t)MROWS*DMODEL ];      // token stream (196)
__device__ __align__(16) float g_xz [2][ (size_t)MROWS*XZ_LD ];    // in-proj out (padded)
__device__ __align__(16) float g_xc [2][ (size_t)MROWS*DINNER ];   // conv+silu
__device__ __align__(16) float g_xd [2][ (size_t)MROWS*XD_LD ];    // x_dbl (padded)
__device__ __align__(16) float g_dl [2][ (size_t)MROWS*DINNER ];   // delta (softplus)
__device__ __align__(16) float g_BC [2][ (size_t)MROWS*32 ];       // [B(16) C(16)] aligned
__device__ __align__(16) float g_y  [2][ (size_t)MROWS*DINNER ];   // scan out (gated)
__device__ __align__(16) float g_do [2][ (size_t)MROWS*DO_LD ];    // out-proj (padded)
__device__ __align__(16) float g_stok[ MROWS ];                    // per-token cls partial

// chunked-scan intermediates: [z][b][chunk][d][16 states]
__device__ __align__(16) float g_hloc[2][BATCH][NCHUNK][DINNER][DSTATE];
__device__ __align__(16) float g_Pc  [2][BATCH][NCHUNK][DINNER][DSTATE];
__device__ __align__(16) float g_hin [2][BATCH][NCHUNK][DINNER][DSTATE];

__device__ __forceinline__ float to_tf32(float x)
{
    float r;
    asm("cvt.rna.tf32.f32 %0, %1;" : "=f"(r) : "f"(x));
    return r;
}

// ---------------------------------------------------------------------------
// cp.async helpers
// ---------------------------------------------------------------------------
__device__ __forceinline__ void cp16(unsigned int dst, const void* src, int sz)
{
    asm volatile("cp.async.cg.shared.global [%0], [%1], 16, %2;\n"
                 :: "r"(dst), "l"(src), "r"(sz));
}
#define CP_COMMIT()  asm volatile("cp.async.commit_group;\n")
#define CP_WAIT0()   asm volatile("cp.async.wait_group 0;\n")
#define CP_WAIT1()   asm volatile("cp.async.wait_group 1;\n")

// ---------------------------------------------------------------------------
// tf32 WMMA GEMM, 128xBN tile, BK=32, cp.async double buffer, dynamic smem.
// BN=128: 4 warps (2x2), 64x64 warp tile  -> 16 MMA / 8 frag-loads per kk.
// BN=64:  8 warps (4x2), 32x32 warp tile.
// For which==0 the A-loader gathers patches directly from the input image.
// C[m,n] = sum_k A[m,k] * W[n,k]
// which: 0=patch (A=x gather, C=g_tok) 1=inproj (A=g_h,C=g_xz[z])
//        2=xdbl (A=g_xc[z],C=g_xd[z]) 3=outproj (A=g_y[z],C=g_do[z])
// flipmask bit z: read A rows with t -> 1023-t inside each 1024-row batch.
// ---------------------------------------------------------------------------
#define BK 32
#define SA_LD 36
#define GEMM_SMEM(BN) ((2*128*SA_LD + 2*(BN)*SA_LD)*4)

template<int BN>
__global__ void __launch_bounds__(BN==128 ? 128 : 256)
k_gemm(const float* __restrict__ W0, const float* __restrict__ W1,
       const float* __restrict__ xsrc,
       int which, int N, int K, int ldc, int flipmask)
{
    constexpr int NTH = (BN==128) ? 128 : 256;   // threads per block
    constexpr int MF  = (BN==128) ? 4 : 2;       // m-frags per warp
    constexpr int NF  = 2*(BN/64)/( (BN==128)?1:1 ) == 0 ? 2 : ((BN==128)?4:2); // 4 or 2
    const int z = blockIdx.z;
    const float* __restrict__ W = z ? W1 : W0;
    const float* __restrict__ A;
    float* __restrict__ C;
    if      (which == 0) { A = xsrc;    C = g_tok;   }
    else if (which == 1) { A = g_h;     C = g_xz[z]; }
    else if (which == 2) { A = g_xc[z]; C = g_xd[z]; }
    else                 { A = g_y[z];  C = g_do[z]; }
    const bool flip = (flipmask >> z) & 1;

    extern __shared__ float dynsm[];
    float* sAb = dynsm;                       // [2][128][SA_LD]
    float* sBb = dynsm + 2*128*SA_LD;         // [2][BN][SA_LD]

    const int tid = threadIdx.x;
    const int m0 = blockIdx.y * 128;
    const int n0 = blockIdx.x * BN;
    const int wid = tid >> 5;
    const int wm = wid >> 1, wn = wid & 1;    // (2x2) or (4x2) warp grid

    wmma::fragment<wmma::accumulator,16,16,8,float> acc[MF][NF];
    #pragma unroll
    for (int i=0;i<MF;i++)
        #pragma unroll
        for (int j=0;j<NF;j++) wmma::fill_fragment(acc[i][j], 0.f);

    const int nc = (K + BK - 1) / BK;

    auto loadA = [&](int buf, int k0) {
        #pragma unroll
        for (int i=0;i<1024/NTH;i++) {
            int f4 = tid + i*NTH;             // 0..1023 (128 rows x 8 float4)
            int r = f4 >> 3, c4 = f4 & 7;
            int gm = m0 + r, gk = k0 + c4*4;
            unsigned int dst = (unsigned int)__cvta_generic_to_shared(
                &sAb[(buf*128 + r)*SA_LD + c4*4]);
            int sz = (gk < K) ? 16 : 0;
            const float* src;
            if (which == 0) {
                int b = gm >> 10, hw = gm & 1023;
                int hh = hw >> 5, ww = hw & 31;
                int cc = gk >> 6, rr = (gk >> 3) & 7, q = gk & 7;
                src = xsrc + (((size_t)(b*3 + cc)*256 + hh*8 + rr)*256 + ww*8 + q);
            } else {
                int row = flip ? ((gm & ~1023) | (1023 - (gm & 1023))) : gm;
                src = A + (size_t)row * K + gk;
            }
            if (!sz) src = A;
            cp16(dst, src, sz);
        }
    };
    auto loadB = [&](int buf, int k0) {
        #pragma unroll
        for (int i=0;i<(BN*8)/NTH;i++) {
            int f4 = tid + i*NTH;             // 0..BN*8-1
            int r = f4 >> 3, c4 = f4 & 7;
            int gn = n0 + r, gk = k0 + c4*4;
            const float* src = W + (size_t)gn * K + gk;
            int sz = (gn < N && gk < K) ? 16 : 0;
            if (!sz) src = W;
            cp16((unsigned int)__cvta_generic_to_shared(
                &sBb[(buf*BN + r)*SA_LD + c4*4]), src, sz);
        }
    };

    loadA(0, 0); loadB(0, 0); CP_COMMIT();

    for (int c = 0; c < nc; c++) {
        const int cur = c & 1;
        if (c + 1 < nc) {
            loadA(cur ^ 1, (c+1)*BK);
            loadB(cur ^ 1, (c+1)*BK);
            CP_COMMIT();
            CP_WAIT1();
        } else {
            CP_WAIT0();
        }
        __syncthreads();

        #pragma unroll
        for (int kk = 0; kk < BK; kk += 8) {
            wmma::fragment<wmma::matrix_a,16,16,8,wmma::precision::tf32,wmma::row_major> fa[MF];
            wmma::fragment<wmma::matrix_b,16,16,8,wmma::precision::tf32,wmma::col_major> fb[NF];
            #pragma unroll
            for (int i=0;i<MF;i++)
                wmma::load_matrix_sync(fa[i], &sAb[(cur*128 + wm*(MF*16) + i*16)*SA_LD + kk], SA_LD);
            #pragma unroll
            for (int j=0;j<NF;j++)
                wmma::load_matrix_sync(fb[j], &sBb[(cur*BN + wn*(NF*16) + j*16)*SA_LD + kk], SA_LD);
            #pragma unroll
            for (int i=0;i<MF;i++)
                #pragma unroll
                for (int j=0;j<NF;j++)
                    wmma::mma_sync(acc[i][j], fa[i], fb[j], acc[i][j]);
        }
        __syncthreads();
    }

    #pragma unroll
    for (int i=0;i<MF;i++)
        #pragma unroll
        for (int j=0;j<NF;j++)
            wmma::store_matrix_sync(&C[(size_t)(m0 + wm*(MF*16) + i*16) * ldc + (n0 + wn*(NF*16) + j*16)],
                                    acc[i][j], ldc, wmma::mem_row_major);
}

// ---------------------------------------------------------------------------
// LN + SiLU + positional encodings -> g_h. Warp-per-row (no block barriers).
// ---------------------------------------------------------------------------
__global__ void k_lnpe(const float* __restrict__ pb, const float* __restrict__ g,
                       const float* __restrict__ bb)
{
    const int m = blockIdx.x*8 + (threadIdx.x >> 5);
    const int lane = threadIdx.x & 31;
    float v[6];
    float s = 0.f, sq = 0.f;
    #pragma unroll
    for (int i=0;i<6;i++){
        int e = lane + 32*i;
        v[i] = g_tok[(size_t)m*EDIM + e] + pb[e];
        s += v[i]; sq += v[i]*v[i];
    }
    #pragma unroll
    for (int o=16;o;o>>=1){ s += __shfl_xor_sync(~0u, s, o); sq += __shfl_xor_sync(~0u, sq, o); }
    float mean = s * (1.f/EDIM);
    float var  = sq * (1.f/EDIM) - mean*mean;
    float rs = rsqrtf(var + 1e-5f);
    #pragma unroll
    for (int i=0;i<6;i++){
        int e = lane + 32*i;
        float u = (v[i]-mean)*rs*g[e] + bb[e];
        g_h[(size_t)m*DMODEL + e] = to_tf32(u / (1.f + __expf(-u)));
    }
    if (lane < 4) {
        int t = m & 1023;
        const float sc = 6.283185307179586f / 32.f;
        float val;
        if      (lane==0) val = sinf((float)t * sc);
        else if (lane==1) val = cosf((float)t * sc);
        else if (lane==2) val = sinf((float)(t>>5) * sc);
        else              val = cosf((float)(t>>5) * sc);
        g_h[(size_t)m*DMODEL + EDIM + lane] = to_tf32(val);
    }
}

// ---------------------------------------------------------------------------
// Causal depthwise conv (width 4) + bias + SiLU, t-blocked: each thread
// computes 8 consecutive timesteps of one channel (11 loads for 8 outputs).
// ---------------------------------------------------------------------------
__global__ void k_conv(const float* __restrict__ cw0, const float* __restrict__ cb0,
                       const float* __restrict__ cw1, const float* __restrict__ cb1)
{
    const int z = blockIdx.z;
    const int b = blockIdx.y;
    const int t0 = blockIdx.x * 8;
    const int d = threadIdx.x;            // 392 threads
    const float* __restrict__ cw = z ? cw1 : cw0;
    const float* __restrict__ cb = z ? cb1 : cb0;

    const float* base = g_xz[z] + ((size_t)(b*LSEQ + t0) * XZ_LD + d);
    float v[11];
    #pragma unroll
    for (int i=0;i<11;i++){
        int t = t0 + i - 3;
        v[i] = (t >= 0) ? base[(long)(i-3) * XZ_LD] : 0.f;
    }
    const float w0 = cw[d*4+0], w1 = cw[d*4+1], w2 = cw[d*4+2], w3 = cw[d*4+3];
    const float bias = cb[d];
    float* outp = g_xc[z] + ((size_t)(b*LSEQ + t0) * DINNER + d);
    #pragma unroll
    for (int j=0;j<8;j++){
        float acc = bias;
        acc = fmaf(w3, v[j+3], acc);
        acc = fmaf(w2, v[j+2], acc);
        acc = fmaf(w1, v[j+1], acc);
        acc = fmaf(w0, v[j  ], acc);
        outp[(size_t)j*DINNER] = to_tf32(acc / (1.f + __expf(-acc)));   // silu
    }
}

// ---------------------------------------------------------------------------
// delta = softplus(x_dbl[:,:13] @ dt_w.T + dt_b); also copy B,C into aligned g_BC
// ---------------------------------------------------------------------------
__global__ void k_deltabc(const float* __restrict__ dtw0, const float* __restrict__ dtb0,
                          const float* __restrict__ dtw1, const float* __restrict__ dtb1)
{
    const int z = blockIdx.z;
    const float* __restrict__ dtw = z ? dtw1 : dtw0;
    const float* __restrict__ dtb = z ? dtb1 : dtb0;
    long idx = (long)blockIdx.x*256 + threadIdx.x;
    if (idx >= (long)MROWS*DINNER) return;
    int m  = (int)(idx / DINNER);
    int dd = (int)(idx % DINNER);
    const float* xd = &g_xd[z][(size_t)m*XD_LD];
    float a = dtb[dd];
    #pragma unroll
    for (int r=0;r<DTRANK;r++) a = fmaf(xd[r], dtw[dd*DTRANK + r], a);
    float sp = fmaxf(a, 0.f) + log1pf(__expf(-fabsf(a)));
    g_dl[z][(size_t)m*DINNER + dd] = sp;
    if (dd < 32) g_BC[z][(size_t)m*32 + dd] = xd[DTRANK + dd];   // 13..44 = B(16),C(16)
}

// ---------------------------------------------------------------------------
// dA helper: structured A (A[n] = -(n+1)) uses one exp; generic uses 16.
// ---------------------------------------------------------------------------
template<bool STRUCT>
__device__ __forceinline__ void compute_dA(float dt, const float* __restrict__ A, float* dA)
{
    if (STRUCT) {
        const float r = __expf(-dt);
        const float r2 = r*r, r4 = r2*r2, r8 = r4*r4;
        dA[0]=r;       dA[1]=r2;      dA[2]=r2*r;      dA[3]=r4;
        dA[4]=r4*r;    dA[5]=r4*r2;   dA[6]=r4*dA[2];  dA[7]=r8;
        dA[8]=r8*r;    dA[9]=r8*r2;   dA[10]=r8*dA[2]; dA[11]=r8*r4;
        dA[12]=r8*dA[4]; dA[13]=r8*dA[5]; dA[14]=r8*dA[6]; dA[15]=r8*r8;
    } else {
        #pragma unroll
        for (int n=0;n<16;n++) dA[n] = __expf(dt * A[n]);
    }
}

__device__ __forceinline__ bool load_A(const float* __restrict__ al, int d, float* A)
{
    bool structured = true;
    #pragma unroll
    for (int n=0;n<16;n++){
        A[n] = -__expf(al[d*16+n]);
        structured = structured && (fabsf(A[n] + (float)(n+1)) < 1e-3f*(float)(n+1));
    }
    return structured;
}

// ---------------------------------------------------------------------------
// Chunked scan pass 1: local scan from h=0 over 64 steps -> h_loc, P.
// ---------------------------------------------------------------------------
template<bool STRUCT>
__device__ __forceinline__ void scan1_loop(int z, int b, int c, int d,
                                           const float* __restrict__ A)
{
    const float* __restrict__ dP  = g_dl[z];
    const float* __restrict__ xcP = g_xc[z];
    const float4* __restrict__ bcP = (const float4*)g_BC[z];

    float h[16], P[16];
    #pragma unroll
    for (int n=0;n<16;n++){ h[n]=0.f; P[n]=1.f; }
    const size_t rowbase = (size_t)b * LSEQ + (size_t)c * CLEN;

    for (int t=0; t<CLEN; t++){
        const size_t row = rowbase + t;
        const float dt = dP [row*DINNER + d];
        const float xc = xcP[row*DINNER + d];
        const float4 B0 = bcP[row*8+0], B1 = bcP[row*8+1], B2 = bcP[row*8+2], B3 = bcP[row*8+3];
        const float du = dt * xc;
        float dA[16];
        compute_dA<STRUCT>(dt, A, dA);
        const float Bv[16] = {B0.x,B0.y,B0.z,B0.w, B1.x,B1.y,B1.z,B1.w,
                              B2.x,B2.y,B2.z,B2.w, B3.x,B3.y,B3.z,B3.w};
        #pragma unroll
        for (int n=0;n<16;n++){
            h[n] = fmaf(dA[n], h[n], du * Bv[n]);
            P[n] *= dA[n];
        }
    }
    float4* hl = (float4*)&g_hloc[z][b][c][d][0];
    float4* pc = (float4*)&g_Pc  [z][b][c][d][0];
    #pragma unroll
    for (int q=0;q<4;q++){
        hl[q] = make_float4(h[q*4], h[q*4+1], h[q*4+2], h[q*4+3]);
        pc[q] = make_float4(P[q*4], P[q*4+1], P[q*4+2], P[q*4+3]);
    }
}

__global__ void k_scan1(const float* __restrict__ al0, const float* __restrict__ al1)
{
    const int z = blockIdx.z;
    const int bc = blockIdx.y;
    const int b = bc >> 4, c = bc & 15;
    const int d = blockIdx.x*128 + threadIdx.x;
    if (d >= DINNER) return;
    float A[16];
    bool s = load_A(z ? al1 : al0, d, A);
    if (s) scan1_loop<true >(z, b, c, d, A);
    else   scan1_loop<false>(z, b, c, d, A);
}

// ---------------------------------------------------------------------------
// Chunked scan pass 2: combine 16 chunks sequentially -> h_in per chunk.
// ---------------------------------------------------------------------------
__global__ void k_scarry()
{
    const int z = blockIdx.z;
    const int b = blockIdx.y;
    const int d = blockIdx.x*128 + threadIdx.x;
    if (d >= DINNER) return;

    float h[16];
    #pragma unroll
    for (int n=0;n<16;n++) h[n] = 0.f;

    for (int c=0;c<NCHUNK;c++){
        float4* hi = (float4*)&g_hin[z][b][c][d][0];
        const float4* hl = (const float4*)&g_hloc[z][b][c][d][0];
        const float4* pc = (const float4*)&g_Pc  [z][b][c][d][0];
        #pragma unroll
        for (int q=0;q<4;q++){
            hi[q] = make_float4(h[q*4], h[q*4+1], h[q*4+2], h[q*4+3]);
            float4 L = hl[q], Pv = pc[q];
            h[q*4+0] = fmaf(Pv.x, h[q*4+0], L.x);
            h[q*4+1] = fmaf(Pv.y, h[q*4+1], L.y);
            h[q*4+2] = fmaf(Pv.z, h[q*4+2], L.z);
            h[q*4+3] = fmaf(Pv.w, h[q*4+3], L.w);
        }
    }
}

// ---------------------------------------------------------------------------
// Chunked scan pass 3: re-scan from h_in -> y = (C·h + D*xc)*silu(z_gate).
// ---------------------------------------------------------------------------
template<bool STRUCT>
__device__ __forceinline__ void scan3_loop(int z, int b, int c, int d,
                                           const float* __restrict__ A, float Dd)
{
    const float* __restrict__ dP  = g_dl[z];
    const float* __restrict__ xcP = g_xc[z];
    const float* __restrict__ xzP = g_xz[z];
    const float4* __restrict__ bcP = (const float4*)g_BC[z];
    float* __restrict__ yP = g_y[z];

    float h[16];
    {
        const float4* hi = (const float4*)&g_hin[z][b][c][d][0];
        #pragma unroll
        for (int q=0;q<4;q++){
            float4 v = hi[q];
            h[q*4]=v.x; h[q*4+1]=v.y; h[q*4+2]=v.z; h[q*4+3]=v.w;
        }
    }
    const size_t rowbase = (size_t)b * LSEQ + (size_t)c * CLEN;

    for (int t=0; t<CLEN; t++){
        const size_t row = rowbase + t;
        const float dt = dP [row*DINNER + d];
        const float xc = xcP[row*DINNER + d];
        const float zv = xzP[row*XZ_LD + DINNER + d];
        const float4 B0 = bcP[row*8+0], B1 = bcP[row*8+1], B2 = bcP[row*8+2], B3 = bcP[row*8+3];
        const float4 C0 = bcP[row*8+4], C1 = bcP[row*8+5], C2 = bcP[row*8+6], C3 = bcP[row*8+7];
        const float du = dt * xc;
        float dA[16];
        compute_dA<STRUCT>(dt, A, dA);

        float a0=0.f, a1=0.f, a2=0.f, a3=0.f;
        #define STEP(n, Bc, Cc, ac) { \
            h[n] = fmaf(dA[n], h[n], du * (Bc)); \
            ac = fmaf(h[n], (Cc), ac); }
        STEP(0,  B0.x, C0.x, a0) STEP(1,  B0.y, C0.y, a1)
        STEP(2,  B0.z, C0.z, a2) STEP(3,  B0.w, C0.w, a3)
        STEP(4,  B1.x, C1.x, a0) STEP(5,  B1.y, C1.y, a1)
        STEP(6,  B1.z, C1.z, a2) STEP(7,  B1.w, C1.w, a3)
        STEP(8,  B2.x, C2.x, a0) STEP(9,  B2.y, C2.y, a1)
        STEP(10, B2.z, C2.z, a2) STEP(11, B2.w, C2.w, a3)
        STEP(12, B3.x, C3.x, a0) STEP(13, B3.y, C3.y, a1)
        STEP(14, B3.z, C3.z, a2) STEP(15, B3.w, C3.w, a3)
        #undef STEP
        float y = ((a0+a1)+(a2+a3)) + Dd*xc;
        float sg = 1.f / (1.f + __expf(-zv));
        yP[row*DINNER + d] = to_tf32(y * (zv * sg));
    }
}

__global__ void k_scan3(const float* __restrict__ al0, const float* __restrict__ Dp0,
                        const float* __restrict__ al1, const float* __restrict__ Dp1)
{
    const int z = blockIdx.z;
    const int bc = blockIdx.y;
    const int b = bc >> 4, c = bc & 15;
    const int d = blockIdx.x*128 + threadIdx.x;
    if (d >= DINNER) return;
    float A[16];
    bool s = load_A(z ? al1 : al0, d, A);
    const float Dd = (z ? Dp1 : Dp0)[d];
    if (s) scan3_loop<true >(z, b, c, d, A, Dd);
    else   scan3_loop<false>(z, b, c, d, A, Dd);
}

// ---------------------------------------------------------------------------
// Combine directions + LN + SiLU + residual + cls dot. Warp-per-token.
// ---------------------------------------------------------------------------
__global__ void k_combine(const float* __restrict__ blg, const float* __restrict__ blb,
                          const float* __restrict__ cw)
{
    const int m = blockIdx.x*8 + (threadIdx.x >> 5);
    const int lane = threadIdx.x & 31;
    const int mf = (m & ~1023) | (1023 - (m & 1023));
    float u[7];
    float s = 0.f, sq = 0.f;
    #pragma unroll
    for (int i=0;i<7;i++){
        int e = lane + 32*i;
        float x = 0.f;
        if (e < DMODEL){
            float fo = g_do[0][(size_t)m *DO_LD + e];
            float bo = g_do[1][(size_t)mf*DO_LD + e];
            x = 0.5f*(fo + bo);
            s += x; sq += x*x;
        }
        u[i] = x;
    }
    #pragma unroll
    for (int o=16;o;o>>=1){ s += __shfl_xor_sync(~0u, s, o); sq += __shfl_xor_sync(~0u, sq, o); }
    float mean = s * (1.f/DMODEL);
    float var  = sq * (1.f/DMODEL) - mean*mean;
    float rs = rsqrtf(var + 1e-5f);
    float p = 0.f;
    #pragma unroll
    for (int i=0;i<7;i++){
        int e = lane + 32*i;
        if (e < DMODEL){
            float v = (u[i]-mean)*rs*blg[e] + blb[e];
            v = v / (1.f + __expf(-v));                  // silu
            v += g_h[(size_t)m*DMODEL + e];              // residual
            p = fmaf(v, cw[e], p);
        }
    }
    #pragma unroll
    for (int o=16;o;o>>=1) p += __shfl_xor_sync(~0u, p, o);
    if (lane == 0) g_stok[m] = p;
}

__global__ void k_final(const float* __restrict__ cb, float* __restrict__ out)
{
    const int b = blockIdx.x;
    const int tid = threadIdx.x;   // 256
    __shared__ float sm[8];
    float s = 0.f;
    for (int i = tid; i < LSEQ; i += 256) s += g_stok[b*LSEQ + i];
    #pragma unroll
    for (int o=16;o;o>>=1) s += __shfl_xor_sync(~0u, s, o);
    if ((tid&31)==0) sm[tid>>5] = s;
    __syncthreads();
    if (tid == 0){
        float t = 0.f;
        #pragma unroll
        for (int i=0;i<8;i++) t += sm[i];
        out[b] = cb[0] + t * (1.f/LSEQ);
    }
}

// ---------------------------------------------------------------------------
// Host launcher
// ---------------------------------------------------------------------------
extern "C" void kernel_launch(void* const* d_in, const int* in_sizes, int n_in,
                              void* d_out, int out_size)
{
    const float* p[27];
    for (int i=0;i<27 && i<n_in;i++) p[i] = (const float*)d_in[i];

    const float *x, *pw, *pb, *peg, *peb, *blg, *blb, *cw, *cb;
    const float *fw[9], *bw[9];
    // fw/bw order: in_w, conv_w, conv_b, xp_w, dt_w, dt_b, A_log, D, out_w
    if (in_sizes[5] == XZ_N*DMODEL) {
        x=p[0]; pw=p[1]; pb=p[2]; peg=p[3]; peb=p[4];
        for (int i=0;i<9;i++){ fw[i]=p[5+i]; bw[i]=p[14+i]; }
        blg=p[23]; blb=p[24]; cw=p[25]; cb=p[26];
    } else {
        x=p[0]; pw=p[1]; pb=p[2]; peg=p[3]; peb=p[4];
        blg=p[5]; blb=p[6]; cw=p[7]; cb=p[8];
        for (int i=0;i<9;i++){ fw[i]=p[9+i]; bw[i]=p[18+i]; }
    }
    float* out = (float*)d_out;

    static bool attr_set = false;
    if (!attr_set) {
        cudaFuncSetAttribute(k_gemm<64>,  cudaFuncAttributeMaxDynamicSharedMemorySize, GEMM_SMEM(64));
        cudaFuncSetAttribute(k_gemm<128>, cudaFuncAttributeMaxDynamicSharedMemorySize, GEMM_SMEM(128));
        attr_set = true;
    }

    // 1. patch embed GEMM (fused gather): M=16384, N=192, K=192
    k_gemm<64><<<dim3(3, MROWS/128, 1), 256, GEMM_SMEM(64)>>>(pw, pw, x, 0, EDIM, EDIM, EDIM, 0);
    // 2. LN + silu + positional enc (warp per row)
    k_lnpe<<<MROWS/8, 256>>>(pb, peg, peb);
    // 3. in-proj both dirs: N=784, K=196; backward (z=1) reads flipped rows
    k_gemm<128><<<dim3(7, MROWS/128, 2), 128, GEMM_SMEM(128)>>>(fw[0], bw[0], x, 1, XZ_N, DMODEL, XZ_LD, 2);
    // 4. depthwise conv + silu (t-blocked: 8 timesteps/thread)
    k_conv<<<dim3(LSEQ/8, BATCH, 2), DINNER>>>(fw[1], fw[2], bw[1], bw[2]);
    // 5. x_dbl GEMM: N=45, K=392
    k_gemm<64><<<dim3(1, MROWS/128, 2), 256, GEMM_SMEM(64)>>>(fw[3], bw[3], x, 2, DTRANK + 2*DSTATE, DINNER, XD_LD, 0);
    // 6. delta (softplus) + pack B,C
    {
        long n = (long)MROWS*DINNER;
        k_deltabc<<<dim3((unsigned)((n + 255)/256), 1, 2), 256>>>(fw[4], fw[5], bw[4], bw[5]);
    }
    // 7. chunked selective scan (both dirs): local -> carry -> final
    k_scan1 <<<dim3((DINNER + 127)/128, BATCH*NCHUNK, 2), 128>>>(fw[6], bw[6]);
    k_scarry<<<dim3((DINNER + 127)/128, BATCH,        2), 128>>>();
    k_scan3 <<<dim3((DINNER + 127)/128, BATCH*NCHUNK, 2), 128>>>(fw[6], fw[7], bw[6], bw[7]);
    // 8. out-proj: N=196, K=392
    k_gemm<128><<<dim3(2, MROWS/128, 2), 128, GEMM_SMEM(128)>>>(fw[8], bw[8], x, 3, DMODEL, DINNER, DO_LD, 0);
    // 9. combine + LN + silu + residual + cls dot per token (warp per token)
    k_combine<<<MROWS/8, 256>>>(blg, blb, cw);
    // 10. final reduction over tokens
    k_final<<<BATCH, 256>>>(cb, out);
}

// round 12
// speedup vs baseline: 1.5639x; 1.1227x over previous
#include <cuda_runtime.h>
#include <cuda_bf16.h>
#include <cstdint>
#include <mma.h>

using namespace nvcuda;

// ---------------------------------------------------------------------------
// Problem constants
// ---------------------------------------------------------------------------
#define BATCH 16
#define LSEQ  1024
#define MROWS (BATCH*LSEQ)     // 16384
#define EDIM  192
#define DMODEL 196
#define DINNER 392
#define DSTATE 16
#define DTRANK 13
#define XZ_N   784             // 2*DINNER
#define XZ_LD  896             // 7 tiles of 128
#define DO_LD  256             // out-proj padded N (196 -> 2*128)
#define NCHUNK 16
#define CLEN   (LSEQ/NCHUNK)   // 64

// ---------------------------------------------------------------------------
// Scratch (device globals: allocation-free per harness rules)
// ---------------------------------------------------------------------------
__device__ __align__(16) float g_tok[ (size_t)MROWS*EDIM ];        // patch-embed out
__device__ __align__(16) float g_h  [ (size_t)MROWS*DMODEL ];      // token stream (196)
__device__ __align__(16) float g_xz [2][ (size_t)MROWS*XZ_LD ];    // in-proj out (padded)
__device__ __align__(16) float g_xc [2][ (size_t)MROWS*DINNER ];   // conv+silu
__device__ __align__(16) float g_dl [2][ (size_t)MROWS*DINNER ];   // delta (softplus)
__device__ __align__(16) float g_BC [2][ (size_t)MROWS*32 ];       // [B(16) C(16)] aligned
__device__ __align__(16) float g_y  [2][ (size_t)MROWS*DINNER ];   // scan out (gated)
__device__ __align__(16) float g_do [2][ (size_t)MROWS*DO_LD ];    // out-proj (padded)
__device__ __align__(16) float g_stok[ MROWS ];                    // per-token cls partial

// chunked-scan intermediates: [z][b][chunk][d][16 states]
__device__ __align__(16) float g_hloc[2][BATCH][NCHUNK][DINNER][DSTATE];
__device__ __align__(16) float g_Pc  [2][BATCH][NCHUNK][DINNER][DSTATE];
__device__ __align__(16) float g_hin [2][BATCH][NCHUNK][DINNER][DSTATE];

__device__ __forceinline__ float to_tf32(float x)
{
    float r;
    asm("cvt.rna.tf32.f32 %0, %1;" : "=f"(r) : "f"(x));
    return r;
}

// ---------------------------------------------------------------------------
// cp.async helpers
// ---------------------------------------------------------------------------
__device__ __forceinline__ void cp16(unsigned int dst, const void* src, int sz)
{
    asm volatile("cp.async.cg.shared.global [%0], [%1], 16, %2;\n"
                 :: "r"(dst), "l"(src), "r"(sz));
}
#define CP_COMMIT()  asm volatile("cp.async.commit_group;\n")
#define CP_WAIT0()   asm volatile("cp.async.wait_group 0;\n")
#define CP_WAIT1()   asm volatile("cp.async.wait_group 1;\n")

// ---------------------------------------------------------------------------
// tf32 WMMA GEMM, 128xBN tile, BK=32, cp.async double buffer, dynamic smem.
// BN=128: 4 warps (2x2), 64x64 warp tile. BN=64: 8 warps (4x2), 32x32.
// which: 0=patch (A=x gather, C=g_tok) 1=inproj (A=g_h,C=g_xz[z])
//        3=outproj (A=g_y[z],C=g_do[z])
// flipmask bit z: read A rows with t -> 1023-t inside each 1024-row batch.
// ---------------------------------------------------------------------------
#define BK 32
#define SA_LD 36
#define GEMM_SMEM(BN) ((2*128*SA_LD + 2*(BN)*SA_LD)*4)

template<int BN>
__global__ void __launch_bounds__(BN==128 ? 128 : 256)
k_gemm(const float* __restrict__ W0, const float* __restrict__ W1,
       const float* __restrict__ xsrc,
       int which, int N, int K, int ldc, int flipmask)
{
    constexpr int NTH = (BN==128) ? 128 : 256;   // threads per block
    constexpr int MF  = (BN==128) ? 4 : 2;       // m-frags per warp
    constexpr int NF  = (BN==128) ? 4 : 2;       // n-frags per warp
    const int z = blockIdx.z;
    const float* __restrict__ W = z ? W1 : W0;
    const float* __restrict__ A;
    float* __restrict__ C;
    if      (which == 0) { A = xsrc;    C = g_tok;   }
    else if (which == 1) { A = g_h;     C = g_xz[z]; }
    else                 { A = g_y[z];  C = g_do[z]; }
    const bool flip = (flipmask >> z) & 1;

    extern __shared__ float dynsm[];
    float* sAb = dynsm;                       // [2][128][SA_LD]
    float* sBb = dynsm + 2*128*SA_LD;         // [2][BN][SA_LD]

    const int tid = threadIdx.x;
    const int m0 = blockIdx.y * 128;
    const int n0 = blockIdx.x * BN;
    const int wid = tid >> 5;
    const int wm = wid >> 1, wn = wid & 1;    // (2x2) or (4x2) warp grid

    wmma::fragment<wmma::accumulator,16,16,8,float> acc[MF][NF];
    #pragma unroll
    for (int i=0;i<MF;i++)
        #pragma unroll
        for (int j=0;j<NF;j++) wmma::fill_fragment(acc[i][j], 0.f);

    const int nc = (K + BK - 1) / BK;

    auto loadA = [&](int buf, int k0) {
        #pragma unroll
        for (int i=0;i<1024/NTH;i++) {
            int f4 = tid + i*NTH;             // 0..1023 (128 rows x 8 float4)
            int r = f4 >> 3, c4 = f4 & 7;
            int gm = m0 + r, gk = k0 + c4*4;
            unsigned int dst = (unsigned int)__cvta_generic_to_shared(
                &sAb[(buf*128 + r)*SA_LD + c4*4]);
            int sz = (gk < K) ? 16 : 0;
            const float* src;
            if (which == 0) {
                int b = gm >> 10, hw = gm & 1023;
                int hh = hw >> 5, ww = hw & 31;
                int cc = gk >> 6, rr = (gk >> 3) & 7, q = gk & 7;
                src = xsrc + (((size_t)(b*3 + cc)*256 + hh*8 + rr)*256 + ww*8 + q);
            } else {
                int row = flip ? ((gm & ~1023) | (1023 - (gm & 1023))) : gm;
                src = A + (size_t)row * K + gk;
            }
            if (!sz) src = A;
            cp16(dst, src, sz);
        }
    };
    auto loadB = [&](int buf, int k0) {
        #pragma unroll
        for (int i=0;i<(BN*8)/NTH;i++) {
            int f4 = tid + i*NTH;             // 0..BN*8-1
            int r = f4 >> 3, c4 = f4 & 7;
            int gn = n0 + r, gk = k0 + c4*4;
            const float* src = W + (size_t)gn * K + gk;
            int sz = (gn < N && gk < K) ? 16 : 0;
            if (!sz) src = W;
            cp16((unsigned int)__cvta_generic_to_shared(
                &sBb[(buf*BN + r)*SA_LD + c4*4]), src, sz);
        }
    };

    loadA(0, 0); loadB(0, 0); CP_COMMIT();

    for (int c = 0; c < nc; c++) {
        const int cur = c & 1;
        if (c + 1 < nc) {
            loadA(cur ^ 1, (c+1)*BK);
            loadB(cur ^ 1, (c+1)*BK);
            CP_COMMIT();
            CP_WAIT1();
        } else {
            CP_WAIT0();
        }
        __syncthreads();

        #pragma unroll
        for (int kk = 0; kk < BK; kk += 8) {
            wmma::fragment<wmma::matrix_a,16,16,8,wmma::precision::tf32,wmma::row_major> fa[MF];
            wmma::fragment<wmma::matrix_b,16,16,8,wmma::precision::tf32,wmma::col_major> fb[NF];
            #pragma unroll
            for (int i=0;i<MF;i++)
                wmma::load_matrix_sync(fa[i], &sAb[(cur*128 + wm*(MF*16) + i*16)*SA_LD + kk], SA_LD);
            #pragma unroll
            for (int j=0;j<NF;j++)
                wmma::load_matrix_sync(fb[j], &sBb[(cur*BN + wn*(NF*16) + j*16)*SA_LD + kk], SA_LD);
            #pragma unroll
            for (int i=0;i<MF;i++)
                #pragma unroll
                for (int j=0;j<NF;j++)
                    wmma::mma_sync(acc[i][j], fa[i], fb[j], acc[i][j]);
        }
        __syncthreads();
    }

    #pragma unroll
    for (int i=0;i<MF;i++)
        #pragma unroll
        for (int j=0;j<NF;j++)
            wmma::store_matrix_sync(&C[(size_t)(m0 + wm*(MF*16) + i*16) * ldc + (n0 + wn*(NF*16) + j*16)],
                                    acc[i][j], ldc, wmma::mem_row_major);
}

// ---------------------------------------------------------------------------
// FUSED x_dbl GEMM + delta/BC epilogue.
// GEMM part: identical arithmetic to the old k_gemm<64> which==2 call
// (M=16384 rows via grid.y, N=45, K=392, BN=64 tile, grid.x=1).
// Epilogue: x_dbl tile -> smem, dt_w -> smem, then per-thread fixed channels
// compute delta = softplus(x_dbl[:, :13] @ dt_w.T + dt_b) and copy B,C.
// No g_xd global round-trip, no separate k_deltabc launch.
// ---------------------------------------------------------------------------
#define XSLD 52
__global__ void __launch_bounds__(256)
k_xdbl(const float* __restrict__ Wx0, const float* __restrict__ Wx1,
       const float* __restrict__ dtw0, const float* __restrict__ dtb0,
       const float* __restrict__ dtw1, const float* __restrict__ dtb1)
{
    const int z = blockIdx.z;
    const float* __restrict__ W   = z ? Wx1 : Wx0;
    const float* __restrict__ dtw = z ? dtw1 : dtw0;
    const float* __restrict__ dtb = z ? dtb1 : dtb0;
    const float* __restrict__ A = g_xc[z];
    const int N = DTRANK + 2*DSTATE;   // 45
    const int K = DINNER;              // 392

    extern __shared__ float dynsm[];
    float* sAb = dynsm;                       // [2][128][SA_LD]
    float* sBb = dynsm + 2*128*SA_LD;         // [2][64][SA_LD]

    const int tid = threadIdx.x;              // 256
    const int m0 = blockIdx.y * 128;
    const int wid = tid >> 5;
    const int wm = wid >> 1, wn = wid & 1;    // 4x2 warp grid, 32x32 tiles

    wmma::fragment<wmma::accumulator,16,16,8,float> acc[2][2];
    #pragma unroll
    for (int i=0;i<2;i++)
        #pragma unroll
        for (int j=0;j<2;j++) wmma::fill_fragment(acc[i][j], 0.f);

    const int nc = (K + BK - 1) / BK;         // 13

    auto loadA = [&](int buf, int k0) {
        #pragma unroll
        for (int i=0;i<4;i++) {
            int f4 = tid + i*256;
            int r = f4 >> 3, c4 = f4 & 7;
            int gm = m0 + r, gk = k0 + c4*4;
            unsigned int dst = (unsigned int)__cvta_generic_to_shared(
                &sAb[(buf*128 + r)*SA_LD + c4*4]);
            int sz = (gk < K) ? 16 : 0;
            const float* src = A + (size_t)gm * K + gk;
            if (!sz) src = A;
            cp16(dst, src, sz);
        }
    };
    auto loadB = [&](int buf, int k0) {
        #pragma unroll
        for (int i=0;i<2;i++) {
            int f4 = tid + i*256;
            int r = f4 >> 3, c4 = f4 & 7;
            int gn = r, gk = k0 + c4*4;
            const float* src = W + (size_t)gn * K + gk;
            int sz = (gn < N && gk < K) ? 16 : 0;
            if (!sz) src = W;
            cp16((unsigned int)__cvta_generic_to_shared(
                &sBb[(buf*64 + r)*SA_LD + c4*4]), src, sz);
        }
    };

    loadA(0, 0); loadB(0, 0); CP_COMMIT();

    for (int c = 0; c < nc; c++) {
        const int cur = c & 1;
        if (c + 1 < nc) {
            loadA(cur ^ 1, (c+1)*BK);
            loadB(cur ^ 1, (c+1)*BK);
            CP_COMMIT();
            CP_WAIT1();
        } else {
            CP_WAIT0();
        }
        __syncthreads();

        #pragma unroll
        for (int kk = 0; kk < BK; kk += 8) {
            wmma::fragment<wmma::matrix_a,16,16,8,wmma::precision::tf32,wmma::row_major> fa[2];
            wmma::fragment<wmma::matrix_b,16,16,8,wmma::precision::tf32,wmma::col_major> fb[2];
            #pragma unroll
            for (int i=0;i<2;i++)
                wmma::load_matrix_sync(fa[i], &sAb[(cur*128 + wm*32 + i*16)*SA_LD + kk], SA_LD);
            #pragma unroll
            for (int j=0;j<2;j++)
                wmma::load_matrix_sync(fb[j], &sBb[(cur*64 + wn*32 + j*16)*SA_LD + kk], SA_LD);
            #pragma unroll
            for (int i=0;i<2;i++)
                #pragma unroll
                for (int j=0;j<2;j++)
                    wmma::mma_sync(acc[i][j], fa[i], fb[j], acc[i][j]);
        }
        __syncthreads();
    }

    // ---- epilogue: x_dbl tile + dt_w into smem ----
    float* sX = dynsm;                    // [128][XSLD]  (26.6 KB)
    float* sW = dynsm + 128*XSLD;         // [392*13]     (20.4 KB)

    for (int i = tid; i < DINNER*DTRANK; i += 256) sW[i] = dtw[i];
    #pragma unroll
    for (int i=0;i<2;i++)
        #pragma unroll
        for (int j=0;j<2;j++){
            int ncol = wn*32 + j*16;
            if (ncol < 48)
                wmma::store_matrix_sync(&sX[(wm*32 + i*16)*XSLD + ncol],
                                        acc[i][j], XSLD, wmma::mem_row_major);
        }
    __syncthreads();

    // thread owns channels d1 = tid, d2 = tid+256 (if < 392); dt_w rows in regs
    const int d1 = tid;
    const int d2 = tid + 256;
    const bool has2 = (d2 < DINNER);
    float w1[DTRANK], w2[DTRANK];
    #pragma unroll
    for (int r=0;r<DTRANK;r++) w1[r] = sW[d1*DTRANK + r];
    const float b1 = dtb[d1];
    float b2 = 0.f;
    if (has2){
        #pragma unroll
        for (int r=0;r<DTRANK;r++) w2[r] = sW[d2*DTRANK + r];
        b2 = dtb[d2];
    }

    for (int row=0; row<128; row++){
        const size_t m = m0 + row;
        float xd[DTRANK];
        #pragma unroll
        for (int r=0;r<DTRANK;r++) xd[r] = sX[row*XSLD + r];   // smem broadcast
        float a = b1;
        #pragma unroll
        for (int r=0;r<DTRANK;r++) a = fmaf(xd[r], w1[r], a);
        g_dl[z][m*DINNER + d1] = fmaxf(a, 0.f) + log1pf(__expf(-fabsf(a)));
        if (has2){
            float a2 = b2;
            #pragma unroll
            for (int r=0;r<DTRANK;r++) a2 = fmaf(xd[r], w2[r], a2);
            g_dl[z][m*DINNER + d2] = fmaxf(a2, 0.f) + log1pf(__expf(-fabsf(a2)));
        }
        if (tid >= 224) {
            int cidx = tid - 224;                              // 0..31
            g_BC[z][m*32 + cidx] = sX[row*XSLD + DTRANK + cidx];
        }
    }
}

// ---------------------------------------------------------------------------
// LN + SiLU + positional encodings -> g_h. Warp-per-row (no block barriers).
// ---------------------------------------------------------------------------
__global__ void k_lnpe(const float* __restrict__ pb, const float* __restrict__ g,
                       const float* __restrict__ bb)
{
    const int m = blockIdx.x*8 + (threadIdx.x >> 5);
    const int lane = threadIdx.x & 31;
    float v[6];
    float s = 0.f, sq = 0.f;
    #pragma unroll
    for (int i=0;i<6;i++){
        int e = lane + 32*i;
        v[i] = g_tok[(size_t)m*EDIM + e] + pb[e];
        s += v[i]; sq += v[i]*v[i];
    }
    #pragma unroll
    for (int o=16;o;o>>=1){ s += __shfl_xor_sync(~0u, s, o); sq += __shfl_xor_sync(~0u, sq, o); }
    float mean = s * (1.f/EDIM);
    float var  = sq * (1.f/EDIM) - mean*mean;
    float rs = rsqrtf(var + 1e-5f);
    #pragma unroll
    for (int i=0;i<6;i++){
        int e = lane + 32*i;
        float u = (v[i]-mean)*rs*g[e] + bb[e];
        g_h[(size_t)m*DMODEL + e] = to_tf32(u / (1.f + __expf(-u)));
    }
    if (lane < 4) {
        int t = m & 1023;
        const float sc = 6.283185307179586f / 32.f;
        float val;
        if      (lane==0) val = sinf((float)t * sc);
        else if (lane==1) val = cosf((float)t * sc);
        else if (lane==2) val = sinf((float)(t>>5) * sc);
        else              val = cosf((float)(t>>5) * sc);
        g_h[(size_t)m*DMODEL + EDIM + lane] = to_tf32(val);
    }
}

// ---------------------------------------------------------------------------
// Causal depthwise conv (width 4) + bias + SiLU, t-blocked: each thread
// computes 8 consecutive timesteps of one channel (11 loads for 8 outputs).
// ---------------------------------------------------------------------------
__global__ void k_conv(const float* __restrict__ cw0, const float* __restrict__ cb0,
                       const float* __restrict__ cw1, const float* __restrict__ cb1)
{
    const int z = blockIdx.z;
    const int b = blockIdx.y;
    const int t0 = blockIdx.x * 8;
    const int d = threadIdx.x;            // 392 threads
    const float* __restrict__ cw = z ? cw1 : cw0;
    const float* __restrict__ cb = z ? cb1 : cb0;

    const float* base = g_xz[z] + ((size_t)(b*LSEQ + t0) * XZ_LD + d);
    float v[11];
    #pragma unroll
    for (int i=0;i<11;i++){
        int t = t0 + i - 3;
        v[i] = (t >= 0) ? base[(long)(i-3) * XZ_LD] : 0.f;
    }
    const float w0 = cw[d*4+0], w1 = cw[d*4+1], w2 = cw[d*4+2], w3 = cw[d*4+3];
    const float bias = cb[d];
    float* outp = g_xc[z] + ((size_t)(b*LSEQ + t0) * DINNER + d);
    #pragma unroll
    for (int j=0;j<8;j++){
        float acc = bias;
        acc = fmaf(w3, v[j+3], acc);
        acc = fmaf(w2, v[j+2], acc);
        acc = fmaf(w1, v[j+1], acc);
        acc = fmaf(w0, v[j  ], acc);
        outp[(size_t)j*DINNER] = to_tf32(acc / (1.f + __expf(-acc)));   // silu
    }
}

// ---------------------------------------------------------------------------
// dA helper: structured A (A[n] = -(n+1)) uses one exp; generic uses 16.
// ---------------------------------------------------------------------------
template<bool STRUCT>
__device__ __forceinline__ void compute_dA(float dt, const float* __restrict__ A, float* dA)
{
    if (STRUCT) {
        const float r = __expf(-dt);
        const float r2 = r*r, r4 = r2*r2, r8 = r4*r4;
        dA[0]=r;       dA[1]=r2;      dA[2]=r2*r;      dA[3]=r4;
        dA[4]=r4*r;    dA[5]=r4*r2;   dA[6]=r4*dA[2];  dA[7]=r8;
        dA[8]=r8*r;    dA[9]=r8*r2;   dA[10]=r8*dA[2]; dA[11]=r8*r4;
        dA[12]=r8*dA[4]; dA[13]=r8*dA[5]; dA[14]=r8*dA[6]; dA[15]=r8*r8;
    } else {
        #pragma unroll
        for (int n=0;n<16;n++) dA[n] = __expf(dt * A[n]);
    }
}

__device__ __forceinline__ bool load_A(const float* __restrict__ al, int d, float* A)
{
    bool structured = true;
    #pragma unroll
    for (int n=0;n<16;n++){
        A[n] = -__expf(al[d*16+n]);
        structured = structured && (fabsf(A[n] + (float)(n+1)) < 1e-3f*(float)(n+1));
    }
    return structured;
}

// ---------------------------------------------------------------------------
// Chunked scan pass 1: local scan from h=0 over 64 steps -> h_loc, P.
// ---------------------------------------------------------------------------
template<bool STRUCT>
__device__ __forceinline__ void scan1_loop(int z, int b, int c, int d,
                                           const float* __restrict__ A)
{
    const float* __restrict__ dP  = g_dl[z];
    const float* __restrict__ xcP = g_xc[z];
    const float4* __restrict__ bcP = (const float4*)g_BC[z];

    float h[16], P[16];
    #pragma unroll
    for (int n=0;n<16;n++){ h[n]=0.f; P[n]=1.f; }
    const size_t rowbase = (size_t)b * LSEQ + (size_t)c * CLEN;

    #pragma unroll 2
    for (int t=0; t<CLEN; t++){
        const size_t row = rowbase + t;
        const float dt = dP [row*DINNER + d];
        const float xc = xcP[row*DINNER + d];
        const float4 B0 = bcP[row*8+0], B1 = bcP[row*8+1], B2 = bcP[row*8+2], B3 = bcP[row*8+3];
        const float du = dt * xc;
        float dA[16];
        compute_dA<STRUCT>(dt, A, dA);
        const float Bv[16] = {B0.x,B0.y,B0.z,B0.w, B1.x,B1.y,B1.z,B1.w,
                              B2.x,B2.y,B2.z,B2.w, B3.x,B3.y,B3.z,B3.w};
        #pragma unroll
        for (int n=0;n<16;n++){
            h[n] = fmaf(dA[n], h[n], du * Bv[n]);
            P[n] *= dA[n];
        }
    }
    float4* hl = (float4*)&g_hloc[z][b][c][d][0];
    float4* pc = (float4*)&g_Pc  [z][b][c][d][0];
    #pragma unroll
    for (int q=0;q<4;q++){
        hl[q] = make_float4(h[q*4], h[q*4+1], h[q*4+2], h[q*4+3]);
        pc[q] = make_float4(P[q*4], P[q*4+1], P[q*4+2], P[q*4+3]);
    }
}

__global__ void k_scan1(const float* __restrict__ al0, const float* __restrict__ al1)
{
    const int z = blockIdx.z;
    const int bc = blockIdx.y;
    const int b = bc >> 4, c = bc & 15;
    const int d = blockIdx.x*128 + threadIdx.x;
    if (d >= DINNER) return;
    float A[16];
    bool s = load_A(z ? al1 : al0, d, A);
    if (s) scan1_loop<true >(z, b, c, d, A);
    else   scan1_loop<false>(z, b, c, d, A);
}

// ---------------------------------------------------------------------------
// Chunked scan pass 2: combine 16 chunks sequentially -> h_in per chunk.
// ---------------------------------------------------------------------------
__global__ void k_scarry()
{
    const int z = blockIdx.z;
    const int b = blockIdx.y;
    const int d = blockIdx.x*128 + threadIdx.x;
    if (d >= DINNER) return;

    float h[16];
    #pragma unroll
    for (int n=0;n<16;n++) h[n] = 0.f;

    for (int c=0;c<NCHUNK;c++){
        float4* hi = (float4*)&g_hin[z][b][c][d][0];
        const float4* hl = (const float4*)&g_hloc[z][b][c][d][0];
        const float4* pc = (const float4*)&g_Pc  [z][b][c][d][0];
        #pragma unroll
        for (int q=0;q<4;q++){
            hi[q] = make_float4(h[q*4], h[q*4+1], h[q*4+2], h[q*4+3]);
            float4 L = hl[q], Pv = pc[q];
            h[q*4+0] = fmaf(Pv.x, h[q*4+0], L.x);
            h[q*4+1] = fmaf(Pv.y, h[q*4+1], L.y);
            h[q*4+2] = fmaf(Pv.z, h[q*4+2], L.z);
            h[q*4+3] = fmaf(Pv.w, h[q*4+3], L.w);
        }
    }
}

// ---------------------------------------------------------------------------
// Chunked scan pass 3: re-scan from h_in -> y = (C·h + D*xc)*silu(z_gate).
// ---------------------------------------------------------------------------
template<bool STRUCT>
__device__ __forceinline__ void scan3_loop(int z, int b, int c, int d,
                                           const float* __restrict__ A, float Dd)
{
    const float* __restrict__ dP  = g_dl[z];
    const float* __restrict__ xcP = g_xc[z];
    const float* __restrict__ xzP = g_xz[z];
    const float4* __restrict__ bcP = (const float4*)g_BC[z];
    float* __restrict__ yP = g_y[z];

    float h[16];
    {
        const float4* hi = (const float4*)&g_hin[z][b][c][d][0];
        #pragma unroll
        for (int q=0;q<4;q++){
            float4 v = hi[q];
            h[q*4]=v.x; h[q*4+1]=v.y; h[q*4+2]=v.z; h[q*4+3]=v.w;
        }
    }
    const size_t rowbase = (size_t)b * LSEQ + (size_t)c * CLEN;

    #pragma unroll 2
    for (int t=0; t<CLEN; t++){
        const size_t row = rowbase + t;
        const float dt = dP [row*DINNER + d];
        const float xc = xcP[row*DINNER + d];
        const float zv = xzP[row*XZ_LD + DINNER + d];
        const float4 B0 = bcP[row*8+0], B1 = bcP[row*8+1], B2 = bcP[row*8+2], B3 = bcP[row*8+3];
        const float4 C0 = bcP[row*8+4], C1 = bcP[row*8+5], C2 = bcP[row*8+6], C3 = bcP[row*8+7];
        const float du = dt * xc;
        float dA[16];
        compute_dA<STRUCT>(dt, A, dA);

        float a0=0.f, a1=0.f, a2=0.f, a3=0.f;
        #define STEP(n, Bc, Cc, ac) { \
            h[n] = fmaf(dA[n], h[n], du * (Bc)); \
            ac = fmaf(h[n], (Cc), ac); }
        STEP(0,  B0.x, C0.x, a0) STEP(1,  B0.y, C0.y, a1)
        STEP(2,  B0.z, C0.z, a2) STEP(3,  B0.w, C0.w, a3)
        STEP(4,  B1.x, C1.x, a0) STEP(5,  B1.y, C1.y, a1)
        STEP(6,  B1.z, C1.z, a2) STEP(7,  B1.w, C1.w, a3)
        STEP(8,  B2.x, C2.x, a0) STEP(9,  B2.y, C2.y, a1)
        STEP(10, B2.z, C2.z, a2) STEP(11, B2.w, C2.w, a3)
        STEP(12, B3.x, C3.x, a0) STEP(13, B3.y, C3.y, a1)
        STEP(14, B3.z, C3.z, a2) STEP(15, B3.w, C3.w, a3)
        #undef STEP
        float y = ((a0+a1)+(a2+a3)) + Dd*xc;
        float sg = 1.f / (1.f + __expf(-zv));
        yP[row*DINNER + d] = to_tf32(y * (zv * sg));
    }
}

__global__ void k_scan3(const float* __restrict__ al0, const float* __restrict__ Dp0,
                        const float* __restrict__ al1, const float* __restrict__ Dp1)
{
    const int z = blockIdx.z;
    const int bc = blockIdx.y;
    const int b = bc >> 4, c = bc & 15;
    const int d = blockIdx.x*128 + threadIdx.x;
    if (d >= DINNER) return;
    float A[16];
    bool s = load_A(z ? al1 : al0, d, A);
    const float Dd = (z ? Dp1 : Dp0)[d];
    if (s) scan3_loop<true >(z, b, c, d, A, Dd);
    else   scan3_loop<false>(z, b, c, d, A, Dd);
}

// ---------------------------------------------------------------------------
// Combine directions + LN + SiLU + residual + cls dot. Warp-per-token.
// ---------------------------------------------------------------------------
__global__ void k_combine(const float* __restrict__ blg, const float* __restrict__ blb,
                          const float* __restrict__ cw)
{
    const int m = blockIdx.x*8 + (threadIdx.x >> 5);
    const int lane = threadIdx.x & 31;
    const int mf = (m & ~1023) | (1023 - (m & 1023));
    float u[7];
    float s = 0.f, sq = 0.f;
    #pragma unroll
    for (int i=0;i<7;i++){
        int e = lane + 32*i;
        float x = 0.f;
        if (e < DMODEL){
            float fo = g_do[0][(size_t)m *DO_LD + e];
            float bo = g_do[1][(size_t)mf*DO_LD + e];
            x = 0.5f*(fo + bo);
            s += x; sq += x*x;
        }
        u[i] = x;
    }
    #pragma unroll
    for (int o=16;o;o>>=1){ s += __shfl_xor_sync(~0u, s, o); sq += __shfl_xor_sync(~0u, sq, o); }
    float mean = s * (1.f/DMODEL);
    float var  = sq * (1.f/DMODEL) - mean*mean;
    float rs = rsqrtf(var + 1e-5f);
    float p = 0.f;
    #pragma unroll
    for (int i=0;i<7;i++){
        int e = lane + 32*i;
        if (e < DMODEL){
            float v = (u[i]-mean)*rs*blg[e] + blb[e];
            v = v / (1.f + __expf(-v));                  // silu
            v += g_h[(size_t)m*DMODEL + e];              // residual
            p = fmaf(v, cw[e], p);
        }
    }
    #pragma unroll
    for (int o=16;o;o>>=1) p += __shfl_xor_sync(~0u, p, o);
    if (lane == 0) g_stok[m] = p;
}

__global__ void k_final(const float* __restrict__ cb, float* __restrict__ out)
{
    const int b = blockIdx.x;
    const int tid = threadIdx.x;   // 256
    __shared__ float sm[8];
    float s = 0.f;
    for (int i = tid; i < LSEQ; i += 256) s += g_stok[b*LSEQ + i];
    #pragma unroll
    for (int o=16;o;o>>=1) s += __shfl_xor_sync(~0u, s, o);
    if ((tid&31)==0) sm[tid>>5] = s;
    __syncthreads();
    if (tid == 0){
        float t = 0.f;
        #pragma unroll
        for (int i=0;i<8;i++) t += sm[i];
        out[b] = cb[0] + t * (1.f/LSEQ);
    }
}

// ---------------------------------------------------------------------------
// Host launcher
// ---------------------------------------------------------------------------
extern "C" void kernel_launch(void* const* d_in, const int* in_sizes, int n_in,
                              void* d_out, int out_size)
{
    const float* p[27];
    for (int i=0;i<27 && i<n_in;i++) p[i] = (const float*)d_in[i];

    const float *x, *pw, *pb, *peg, *peb, *blg, *blb, *cw, *cb;
    const float *fw[9], *bw[9];
    // fw/bw order: in_w, conv_w, conv_b, xp_w, dt_w, dt_b, A_log, D, out_w
    if (in_sizes[5] == XZ_N*DMODEL) {
        x=p[0]; pw=p[1]; pb=p[2]; peg=p[3]; peb=p[4];
        for (int i=0;i<9;i++){ fw[i]=p[5+i]; bw[i]=p[14+i]; }
        blg=p[23]; blb=p[24]; cw=p[25]; cb=p[26];
    } else {
        x=p[0]; pw=p[1]; pb=p[2]; peg=p[3]; peb=p[4];
        blg=p[5]; blb=p[6]; cw=p[7]; cb=p[8];
        for (int i=0;i<9;i++){ fw[i]=p[9+i]; bw[i]=p[18+i]; }
    }
    float* out = (float*)d_out;

    static bool attr_set = false;
    if (!attr_set) {
        cudaFuncSetAttribute(k_gemm<64>,  cudaFuncAttributeMaxDynamicSharedMemorySize, GEMM_SMEM(64));
        cudaFuncSetAttribute(k_gemm<128>, cudaFuncAttributeMaxDynamicSharedMemorySize, GEMM_SMEM(128));
        cudaFuncSetAttribute(k_xdbl,      cudaFuncAttributeMaxDynamicSharedMemorySize, GEMM_SMEM(64));
        attr_set = true;
    }

    // 1. patch embed GEMM (fused gather): M=16384, N=192, K=192
    k_gemm<64><<<dim3(3, MROWS/128, 1), 256, GEMM_SMEM(64)>>>(pw, pw, x, 0, EDIM, EDIM, EDIM, 0);
    // 2. LN + silu + positional enc (warp per row)
    k_lnpe<<<MROWS/8, 256>>>(pb, peg, peb);
    // 3. in-proj both dirs: N=784, K=196; backward (z=1) reads flipped rows
    k_gemm<128><<<dim3(7, MROWS/128, 2), 128, GEMM_SMEM(128)>>>(fw[0], bw[0], x, 1, XZ_N, DMODEL, XZ_LD, 2);
    // 4. depthwise conv + silu (t-blocked: 8 timesteps/thread)
    k_conv<<<dim3(LSEQ/8, BATCH, 2), DINNER>>>(fw[1], fw[2], bw[1], bw[2]);
    // 5. x_dbl GEMM fused with delta/BC epilogue (replaces xdbl GEMM + deltabc)
    k_xdbl<<<dim3(1, MROWS/128, 2), 256, GEMM_SMEM(64)>>>(fw[3], bw[3], fw[4], fw[5], bw[4], bw[5]);
    // 6. chunked selective scan (both dirs): local -> carry -> final
    k_scan1 <<<dim3((DINNER + 127)/128, BATCH*NCHUNK, 2), 128>>>(fw[6], bw[6]);
    k_scarry<<<dim3((DINNER + 127)/128, BATCH,        2), 128>>>();
    k_scan3 <<<dim3((DINNER + 127)/128, BATCH*NCHUNK, 2), 128>>>(fw[6], fw[7], bw[6], bw[7]);
    // 7. out-proj: N=196, K=392
    k_gemm<128><<<dim3(2, MROWS/128, 2), 128, GEMM_SMEM(128)>>>(fw[8], bw[8], x, 3, DMODEL, DINNER, DO_LD, 0);
    // 8. combine + LN + silu + residual + cls dot per token (warp per token)
    k_combine<<<MROWS/8, 256>>>(blg, blb, cw);
    // 9. final reduction over tokens
    k_final<<<BATCH, 256>>>(cb, out);
}